// round 3
// baseline (speedup 1.0000x reference)
#include <cuda_runtime.h>

// Problem constants
#define H 512
#define W 512
#define NC 48              // 16 batch * 3 channels
#define OH 171
#define OW 171
#define GX 43              // pixel-groups per row: 42 groups of 4 + 1 group of 3
#define NGROUPS (NC * OH * GX)   // 352,944
#define TOTAL (NC * OH * OW)     // 1,403,568

__device__ float        g_partial = 0.0f;
__device__ unsigned int g_count   = 0;

__global__ void __launch_bounds__(256) ssim_kernel(
    const float* __restrict__ img1,
    const float* __restrict__ img2,
    const float* __restrict__ window,
    float* __restrict__ out)
{
    const float C1 = 0.0001f;   // 0.01^2
    const float C2 = 0.0009f;   // 0.03^2

    // 3x3 gaussian window (identical per channel) — broadcast, L1-resident
    float w[9];
    #pragma unroll
    for (int i = 0; i < 9; i++) w[i] = __ldg(window + i);

    float acc = 0.0f;

    const int group = blockIdx.x * blockDim.x + threadIdx.x;
    if (group < NGROUPS) {
        const int gx    = group % GX;
        const int t     = group / GX;
        const int oy    = t % OH;
        const int plane = t / OH;

        const int base = 12 * gx;          // first input column of pixel 0's center-1 +1
        const int iy   = 3 * oy - 1;       // first input row of the window
        const int npix = (gx == GX - 1) ? 3 : 4;
        const bool full = (npix == 4);
        const bool has_left = (base > 0);

        const float* __restrict__ p1 = img1 + (size_t)plane * (H * W);
        const float* __restrict__ p2 = img2 + (size_t)plane * (H * W);

        // 5 accumulators x 4 pixels
        float m1[4], m2[4], s11[4], s22[4], s12[4];
        #pragma unroll
        for (int p = 0; p < 4; p++) { m1[p]=0.f; m2[p]=0.f; s11[p]=0.f; s22[p]=0.f; s12[p]=0.f; }

        #pragma unroll
        for (int r = 0; r < 3; r++) {
            const int row = iy + r;
            if (row < 0) continue;          // zero padding row (only when oy==0)

            const float* __restrict__ r1 = p1 + row * W + base;
            const float* __restrict__ r2 = p2 + row * W + base;

            // va[0] = col base-1 (left edge), va[1+j] = col base+j (j=0..10)
            float va[12], vb[12];

            va[0] = has_left ? __ldg(r1 - 1) : 0.f;
            vb[0] = has_left ? __ldg(r2 - 1) : 0.f;

            const float4 a0 = __ldg((const float4*)(r1));
            const float4 b0 = __ldg((const float4*)(r2));
            const float4 a1 = __ldg((const float4*)(r1 + 4));
            const float4 b1 = __ldg((const float4*)(r2 + 4));

            va[1]=a0.x; va[2]=a0.y; va[3]=a0.z; va[4]=a0.w;
            va[5]=a1.x; va[6]=a1.y; va[7]=a1.z; va[8]=a1.w;
            vb[1]=b0.x; vb[2]=b0.y; vb[3]=b0.z; vb[4]=b0.w;
            vb[5]=b1.x; vb[6]=b1.y; vb[7]=b1.z; vb[8]=b1.w;

            if (full) {
                const float4 a2 = __ldg((const float4*)(r1 + 8));
                const float4 b2 = __ldg((const float4*)(r2 + 8));
                va[9]=a2.x; va[10]=a2.y; va[11]=a2.z;   // a2.w = next group's left edge, unused
                vb[9]=b2.x; vb[10]=b2.y; vb[11]=b2.z;
            } else {
                va[9]=va[10]=va[11]=0.f;
                vb[9]=vb[10]=vb[11]=0.f;
            }

            // pixel p tap c -> column index 3p+c in va/vb
            #pragma unroll
            for (int p = 0; p < 4; p++) {
                #pragma unroll
                for (int c = 0; c < 3; c++) {
                    const float wt = w[r * 3 + c];
                    const float a  = va[3 * p + c];
                    const float b  = vb[3 * p + c];
                    const float wa = wt * a;
                    const float wb = wt * b;
                    m1[p]  += wa;
                    m2[p]  += wb;
                    s11[p] = fmaf(wa, a, s11[p]);
                    s22[p] = fmaf(wb, b, s22[p]);
                    s12[p] = fmaf(wa, b, s12[p]);
                }
            }
        }

        #pragma unroll
        for (int p = 0; p < 4; p++) {
            if (p < npix) {
                const float a11 = m1[p] * m1[p];
                const float a22 = m2[p] * m2[p];
                const float a12 = m1[p] * m2[p];
                const float v1  = s11[p] - a11;
                const float v2  = s22[p] - a22;
                const float v12 = s12[p] - a12;
                const float num = (2.0f * a12 + C1) * (2.0f * v12 + C2);
                const float den = (a11 + a22 + C1) * (v1 + v2 + C2);
                acc += num / den;
            }
        }
    }

    // ---- block reduction: warp shuffle -> smem -> warp0 -> one atomic ----
    #pragma unroll
    for (int o = 16; o > 0; o >>= 1)
        acc += __shfl_down_sync(0xffffffffu, acc, o);

    __shared__ float wsum[8];
    const int lane = threadIdx.x & 31;
    const int wid  = threadIdx.x >> 5;
    if (lane == 0) wsum[wid] = acc;
    __syncthreads();

    if (wid == 0) {
        acc = (lane < 8) ? wsum[lane] : 0.0f;
        #pragma unroll
        for (int o = 4; o > 0; o >>= 1)
            acc += __shfl_down_sync(0xffffffffu, acc, o);
        if (lane == 0)
            atomicAdd(&g_partial, acc * (1.0f / (float)TOTAL));
    }

    // ---- last block publishes the result and resets scratch (graph-safe) ----
    __shared__ bool is_last;
    if (threadIdx.x == 0) {
        __threadfence();
        const unsigned prev = atomicAdd(&g_count, 1u);
        is_last = (prev == gridDim.x - 1);
    }
    __syncthreads();
    if (is_last && threadIdx.x == 0) {
        *out      = g_partial;
        g_partial = 0.0f;
        g_count   = 0;
    }
}

extern "C" void kernel_launch(void* const* d_in, const int* in_sizes, int n_in,
                              void* d_out, int out_size)
{
    const float* img1   = (const float*)d_in[0];
    const float* img2   = (const float*)d_in[1];
    const float* window = (const float*)d_in[2];
    float* out = (float*)d_out;

    const int blocks = (NGROUPS + 255) / 256;   // 1379
    ssim_kernel<<<blocks, 256>>>(img1, img2, window, out);
}